// round 10
// baseline (speedup 1.0000x reference)
#include <cuda_runtime.h>
#include <cstdint>

// HorizontalWidthTokenPyramid: x [32, 256, 32, 16, 16] f32
//   -> out [N*C*S, 31, 4] f32
// Per 16x16 slice: for b in {16,8,4,2,1}: bin H (mean+max per col), then
// pool W 16->4 tokens (mean+max). Concat -> 31 bins.
//
// R9: same structure as R6 (cp.async staging -> register fold -> smem
// restage -> coalesced flush) with the ALU stripped out of both hot loops:
//  - cp.async addresses are base + unrolled-constant strides (fold into
//    LDGSTS immediates)
//  - outputs restaged COMPACT (stride 124, proven conflict-free:
//    28*sl+4b+q mod 32 hits all banks) so the flush is a pure linear copy
//    with zero index arithmetic.

namespace {

constexpr int THREADS          = 128;
constexpr int SLICES_PER_BLOCK = 32;
constexpr int SLICE_FLOATS     = 256;            // 16*16
constexpr int SLICE_STRIDE_F   = 272;            // input stride 1088 B (68x16B)
constexpr int OUT_PER_SLICE    = 31 * 4;         // 124
constexpr int BLOCK_OUT_FLOATS = SLICES_PER_BLOCK * OUT_PER_SLICE;  // 3968
constexpr int CHUNKS_PER_THR   = SLICES_PER_BLOCK * 64 / THREADS;   // 16

__device__ __forceinline__ float max4(float a, float b, float c, float d) {
    return fmaxf(fmaxf(a, b), fmaxf(c, d));
}
__device__ __forceinline__ float sum4(float a, float b, float c, float d) {
    return (a + b) + (c + d);
}
// token for a bin: z_c = inv*sum_c + max_c ; out = 0.25*sum(z) + max(z)
__device__ __forceinline__ float token(const float s[4], const float m[4], float inv) {
    const float z0 = inv * s[0] + m[0];
    const float z1 = inv * s[1] + m[1];
    const float z2 = inv * s[2] + m[2];
    const float z3 = inv * s[3] + m[3];
    return 0.25f * sum4(z0, z1, z2, z3) + max4(z0, z1, z2, z3);
}

__global__ __launch_bounds__(THREADS, 6)
void hwtp_kernel(const float4* __restrict__ x4, float* __restrict__ out) {
    __shared__ float smem[SLICES_PER_BLOCK * SLICE_STRIDE_F];  // 34816 B

    const int tid = threadIdx.x;

    // ---- Phase 1: stage 32 slices (32KB) via cp.async.cg ----
    // g = tid + 128k -> slice = (tid>>6) + 2k, chunk = tid&63.
    // All k-dependence is a constant stride: dst += 2176, src += 2048.
    {
        const uint32_t sbase = (uint32_t)__cvta_generic_to_shared(&smem[0]);
        const char* gbase =
            (const char*)(x4 + (long)blockIdx.x * (SLICES_PER_BLOCK * SLICE_FLOATS / 4));
        const uint32_t dst0 = sbase + (uint32_t)(tid >> 6) * 1088u
                                    + (uint32_t)(tid & 63) * 16u;
        const char* src0 = gbase + (long)tid * 16;
        #pragma unroll
        for (int k = 0; k < CHUNKS_PER_THR; ++k) {
            asm volatile("cp.async.cg.shared.global [%0], [%1], 16;\n"
                         :: "r"(dst0 + (uint32_t)(k * 2176)),
                            "l"(src0 + (long)k * 2048));
        }
        asm volatile("cp.async.commit_group;\n" ::: "memory");
        asm volatile("cp.async.wait_group 0;\n" ::: "memory");
    }
    __syncthreads();

    // ---- Phase 2: pyramid fold, outputs buffered in registers ----
    const int sl = tid >> 2;    // local slice 0..31
    const int q  = tid & 3;     // width token 0..3 (cols 4q..4q+3)

    const float* base = &smem[sl * SLICE_STRIDE_F + q * 4];

    float rb[31];               // static indices -> registers
    float s4v[4], m4v[4];       // level b=4 accumulators
    float s2v[4], m2v[4];       // level b=2
    float s1v[4], m1v[4];       // level b=1

    #pragma unroll
    for (int i = 0; i < 8; ++i) {           // row pair: rows 2i, 2i+1
        const float4 v0 = *reinterpret_cast<const float4*>(base + (2 * i) * 16);
        const float4 v1 = *reinterpret_cast<const float4*>(base + (2 * i + 1) * 16);

        // level b=16 (bin of 1 row): z = 2*row
        rb[2 * i]     = 0.5f * sum4(v0.x, v0.y, v0.z, v0.w)
                      + 2.0f * max4(v0.x, v0.y, v0.z, v0.w);
        rb[2 * i + 1] = 0.5f * sum4(v1.x, v1.y, v1.z, v1.w)
                      + 2.0f * max4(v1.x, v1.y, v1.z, v1.w);

        // pair = level b=8 bin
        float ps[4] = { v0.x + v1.x, v0.y + v1.y, v0.z + v1.z, v0.w + v1.w };
        float pm[4] = { fmaxf(v0.x, v1.x), fmaxf(v0.y, v1.y),
                        fmaxf(v0.z, v1.z), fmaxf(v0.w, v1.w) };
        rb[16 + i] = token(ps, pm, 0.5f);

        // fold into level b=4
        if ((i & 1) == 0) {
            #pragma unroll
            for (int c = 0; c < 4; ++c) { s4v[c] = ps[c]; m4v[c] = pm[c]; }
        } else {
            #pragma unroll
            for (int c = 0; c < 4; ++c) {
                s4v[c] += ps[c]; m4v[c] = fmaxf(m4v[c], pm[c]);
            }
            const int j = i >> 1;
            rb[24 + j] = token(s4v, m4v, 0.25f);

            // fold into level b=2
            if ((j & 1) == 0) {
                #pragma unroll
                for (int c = 0; c < 4; ++c) { s2v[c] = s4v[c]; m2v[c] = m4v[c]; }
            } else {
                #pragma unroll
                for (int c = 0; c < 4; ++c) {
                    s2v[c] += s4v[c]; m2v[c] = fmaxf(m2v[c], m4v[c]);
                }
                const int t = j >> 1;
                rb[28 + t] = token(s2v, m2v, 0.125f);

                // fold into level b=1
                if (t == 0) {
                    #pragma unroll
                    for (int c = 0; c < 4; ++c) { s1v[c] = s2v[c]; m1v[c] = m2v[c]; }
                } else {
                    #pragma unroll
                    for (int c = 0; c < 4; ++c) {
                        s1v[c] += s2v[c]; m1v[c] = fmaxf(m1v[c], m2v[c]);
                    }
                    rb[30] = token(s1v, m1v, 0.0625f);
                }
            }
        }
    }

    // All input reads done block-wide before outputs overwrite the region
    // (slice j's compact output range overlaps slice j-1's input).
    __syncthreads();

    // ---- Phase 3: compact restage, conflict-free (28*sl+4b+q mod 32) ----
    {
        float* o = &smem[sl * OUT_PER_SLICE + q];
        #pragma unroll
        for (int b = 0; b < 31; ++b)
            o[b * 4] = rb[b];
    }
    __syncthreads();

    // ---- Phase 4: pure linear coalesced flush (zero index math) ----
    float* ob = out + (long)blockIdx.x * BLOCK_OUT_FLOATS;
    #pragma unroll
    for (int i = 0; i < BLOCK_OUT_FLOATS / THREADS; ++i)     // 31 iters
        __stcs(&ob[i * THREADS + tid], smem[i * THREADS + tid]);
}

}  // namespace

extern "C" void kernel_launch(void* const* d_in, const int* in_sizes, int n_in,
                              void* d_out, int out_size) {
    const float* x = (const float*)d_in[0];
    float* out = (float*)d_out;

    const long total_floats = (long)in_sizes[0];          // 67,108,864
    const long slices = total_floats / SLICE_FLOATS;      // 262,144
    const int blocks = (int)(slices / SLICES_PER_BLOCK);  // 8192

    hwtp_kernel<<<blocks, THREADS>>>(reinterpret_cast<const float4*>(x), out);
}

// round 11
// speedup vs baseline: 1.0073x; 1.0073x over previous
#include <cuda_runtime.h>
#include <cstdint>

// HorizontalWidthTokenPyramid: x [32, 256, 32, 16, 16] f32
//   -> out [N*C*S, 31, 4] f32
// Per 16x16 slice: for b in {16,8,4,2,1}: bin H (mean+max per col), then
// pool W 16->4 tokens (mean+max). Concat -> 31 bins.
//
// R9: same structure as R6 (cp.async staging -> register fold -> smem
// restage -> coalesced flush) with the ALU stripped out of both hot loops:
//  - cp.async addresses are base + unrolled-constant strides (fold into
//    LDGSTS immediates)
//  - outputs restaged COMPACT (stride 124, proven conflict-free:
//    28*sl+4b+q mod 32 hits all banks) so the flush is a pure linear copy
//    with zero index arithmetic.

namespace {

constexpr int THREADS          = 128;
constexpr int SLICES_PER_BLOCK = 32;
constexpr int SLICE_FLOATS     = 256;            // 16*16
constexpr int SLICE_STRIDE_F   = 272;            // input stride 1088 B (68x16B)
constexpr int OUT_PER_SLICE    = 31 * 4;         // 124
constexpr int BLOCK_OUT_FLOATS = SLICES_PER_BLOCK * OUT_PER_SLICE;  // 3968
constexpr int CHUNKS_PER_THR   = SLICES_PER_BLOCK * 64 / THREADS;   // 16

__device__ __forceinline__ float max4(float a, float b, float c, float d) {
    return fmaxf(fmaxf(a, b), fmaxf(c, d));
}
__device__ __forceinline__ float sum4(float a, float b, float c, float d) {
    return (a + b) + (c + d);
}
// token for a bin: z_c = inv*sum_c + max_c ; out = 0.25*sum(z) + max(z)
__device__ __forceinline__ float token(const float s[4], const float m[4], float inv) {
    const float z0 = inv * s[0] + m[0];
    const float z1 = inv * s[1] + m[1];
    const float z2 = inv * s[2] + m[2];
    const float z3 = inv * s[3] + m[3];
    return 0.25f * sum4(z0, z1, z2, z3) + max4(z0, z1, z2, z3);
}

__global__ __launch_bounds__(THREADS, 6)
void hwtp_kernel(const float4* __restrict__ x4, float* __restrict__ out) {
    __shared__ float smem[SLICES_PER_BLOCK * SLICE_STRIDE_F];  // 34816 B

    const int tid = threadIdx.x;

    // ---- Phase 1: stage 32 slices (32KB) via cp.async.cg ----
    // g = tid + 128k -> slice = (tid>>6) + 2k, chunk = tid&63.
    // All k-dependence is a constant stride: dst += 2176, src += 2048.
    {
        const uint32_t sbase = (uint32_t)__cvta_generic_to_shared(&smem[0]);
        const char* gbase =
            (const char*)(x4 + (long)blockIdx.x * (SLICES_PER_BLOCK * SLICE_FLOATS / 4));
        const uint32_t dst0 = sbase + (uint32_t)(tid >> 6) * 1088u
                                    + (uint32_t)(tid & 63) * 16u;
        const char* src0 = gbase + (long)tid * 16;
        #pragma unroll
        for (int k = 0; k < CHUNKS_PER_THR; ++k) {
            asm volatile("cp.async.cg.shared.global [%0], [%1], 16;\n"
                         :: "r"(dst0 + (uint32_t)(k * 2176)),
                            "l"(src0 + (long)k * 2048));
        }
        asm volatile("cp.async.commit_group;\n" ::: "memory");
        asm volatile("cp.async.wait_group 0;\n" ::: "memory");
    }
    __syncthreads();

    // ---- Phase 2: pyramid fold, outputs buffered in registers ----
    const int sl = tid >> 2;    // local slice 0..31
    const int q  = tid & 3;     // width token 0..3 (cols 4q..4q+3)

    const float* base = &smem[sl * SLICE_STRIDE_F + q * 4];

    float rb[31];               // static indices -> registers
    float s4v[4], m4v[4];       // level b=4 accumulators
    float s2v[4], m2v[4];       // level b=2
    float s1v[4], m1v[4];       // level b=1

    #pragma unroll
    for (int i = 0; i < 8; ++i) {           // row pair: rows 2i, 2i+1
        const float4 v0 = *reinterpret_cast<const float4*>(base + (2 * i) * 16);
        const float4 v1 = *reinterpret_cast<const float4*>(base + (2 * i + 1) * 16);

        // level b=16 (bin of 1 row): z = 2*row
        rb[2 * i]     = 0.5f * sum4(v0.x, v0.y, v0.z, v0.w)
                      + 2.0f * max4(v0.x, v0.y, v0.z, v0.w);
        rb[2 * i + 1] = 0.5f * sum4(v1.x, v1.y, v1.z, v1.w)
                      + 2.0f * max4(v1.x, v1.y, v1.z, v1.w);

        // pair = level b=8 bin
        float ps[4] = { v0.x + v1.x, v0.y + v1.y, v0.z + v1.z, v0.w + v1.w };
        float pm[4] = { fmaxf(v0.x, v1.x), fmaxf(v0.y, v1.y),
                        fmaxf(v0.z, v1.z), fmaxf(v0.w, v1.w) };
        rb[16 + i] = token(ps, pm, 0.5f);

        // fold into level b=4
        if ((i & 1) == 0) {
            #pragma unroll
            for (int c = 0; c < 4; ++c) { s4v[c] = ps[c]; m4v[c] = pm[c]; }
        } else {
            #pragma unroll
            for (int c = 0; c < 4; ++c) {
                s4v[c] += ps[c]; m4v[c] = fmaxf(m4v[c], pm[c]);
            }
            const int j = i >> 1;
            rb[24 + j] = token(s4v, m4v, 0.25f);

            // fold into level b=2
            if ((j & 1) == 0) {
                #pragma unroll
                for (int c = 0; c < 4; ++c) { s2v[c] = s4v[c]; m2v[c] = m4v[c]; }
            } else {
                #pragma unroll
                for (int c = 0; c < 4; ++c) {
                    s2v[c] += s4v[c]; m2v[c] = fmaxf(m2v[c], m4v[c]);
                }
                const int t = j >> 1;
                rb[28 + t] = token(s2v, m2v, 0.125f);

                // fold into level b=1
                if (t == 0) {
                    #pragma unroll
                    for (int c = 0; c < 4; ++c) { s1v[c] = s2v[c]; m1v[c] = m2v[c]; }
                } else {
                    #pragma unroll
                    for (int c = 0; c < 4; ++c) {
                        s1v[c] += s2v[c]; m1v[c] = fmaxf(m1v[c], m2v[c]);
                    }
                    rb[30] = token(s1v, m1v, 0.0625f);
                }
            }
        }
    }

    // All input reads done block-wide before outputs overwrite the region
    // (slice j's compact output range overlaps slice j-1's input).
    __syncthreads();

    // ---- Phase 3: compact restage, conflict-free (28*sl+4b+q mod 32) ----
    {
        float* o = &smem[sl * OUT_PER_SLICE + q];
        #pragma unroll
        for (int b = 0; b < 31; ++b)
            o[b * 4] = rb[b];
    }
    __syncthreads();

    // ---- Phase 4: pure linear coalesced flush (zero index math) ----
    float* ob = out + (long)blockIdx.x * BLOCK_OUT_FLOATS;
    #pragma unroll
    for (int i = 0; i < BLOCK_OUT_FLOATS / THREADS; ++i)     // 31 iters
        __stcs(&ob[i * THREADS + tid], smem[i * THREADS + tid]);
}

}  // namespace

extern "C" void kernel_launch(void* const* d_in, const int* in_sizes, int n_in,
                              void* d_out, int out_size) {
    const float* x = (const float*)d_in[0];
    float* out = (float*)d_out;

    const long total_floats = (long)in_sizes[0];          // 67,108,864
    const long slices = total_floats / SLICE_FLOATS;      // 262,144
    const int blocks = (int)(slices / SLICES_PER_BLOCK);  // 8192

    hwtp_kernel<<<blocks, THREADS>>>(reinterpret_cast<const float4*>(x), out);
}